// round 11
// baseline (speedup 1.0000x reference)
#include <cuda_runtime.h>
#include <cstdint>

// 2x2 Haar inverse reconstruction:
//   x: (32, 4, 512, 512) f32  ->  out: (32, 1, 1024, 1024) f32
//   L0=R*a+R*b; L1=R*a-R*b; H0=R*c+R*d; H1=R*c-R*d
//   out[2h,2w]=R*(L0+H0)  out[2h,2w+1]=R*(L0-H0)
//   out[2h+1,2w]=R*(L1+H1)  out[2h+1,2w+1]=R*(L1-H1)
//
// R11: both streams batched.
//   reads : load phase — each warp reads one (channel,row) = 2KB CONTIGUOUS
//           (4 dense 512B LDG.128.cs) into smem.
//   writes: one 16KB cp.async.bulk per CTA (the R5 win).
// The 16KB smem buffer is reused: input pair staged -> regs -> same buffer
// becomes the output staging area. smem/CTA = 16KB -> 8 CTAs/SM.

#define RCONST 0.70710678118654752440f

static constexpr int S = 512;     // input spatial
static constexpr int NIMG = 32;   // batch

__device__ __forceinline__ void haar4(float a, float b, float c, float d,
                                      float& o00, float& o01, float& o10, float& o11) {
    float l0 = RCONST * a + RCONST * b;
    float l1 = RCONST * a - RCONST * b;
    float h0 = RCONST * c + RCONST * d;
    float h1 = RCONST * c - RCONST * d;
    o00 = RCONST * l0 + RCONST * h0;
    o01 = RCONST * l0 - RCONST * h0;
    o10 = RCONST * l1 + RCONST * h1;
    o11 = RCONST * l1 - RCONST * h1;
}

__device__ __forceinline__ uint32_t smem_u32(const void* p) {
    uint32_t a;
    asm("{ .reg .u64 t; cvta.to.shared.u64 t, %1; cvt.u32.u64 %0, t; }"
        : "=r"(a) : "l"(p));
    return a;
}

__global__ __launch_bounds__(256)
void haar_recon_kernel(const float* __restrict__ x, float* __restrict__ out) {
    // 16KB, reused: phase A = sin[ch][row][512]; phase B = sout[4][1024]
    __shared__ alignas(16) float sbuf[4 * 2 * S];

    unsigned t    = threadIdx.x;
    unsigned b    = blockIdx.x;
    unsigned lane = t & 31;
    unsigned cr   = t >> 5;        // warp id 0..7 -> (ch, row-in-pair)
    unsigned ch   = cr >> 1;       // channel 0..3
    unsigned rw   = cr & 1;        // row within pair 0..1
    unsigned k    = b & 255;       // row-pair index (input rows 2k, 2k+1)
    unsigned n    = b >> 8;        // image

    // ---- load phase: warp cr reads 2KB contiguous (channel ch, row 2k+rw) ----
    const float4* src = (const float4*)(x + ((size_t)n * 4 + ch) * S * S
                                          + (size_t)(2 * k + rw) * S);
    float4 v0 = __ldcs(src + lane);
    float4 v1 = __ldcs(src + lane + 32);
    float4 v2 = __ldcs(src + lane + 64);
    float4 v3 = __ldcs(src + lane + 96);

    float4* srow = (float4*)sbuf + cr * 128;   // sin[ch][rw], 512 floats
    srow[lane]      = v0;
    srow[lane + 32] = v1;
    srow[lane + 64] = v2;
    srow[lane + 96] = v3;

    __syncthreads();

    // ---- gather a,b,c,d for this thread's pixels into registers ----
    unsigned wq = t & 127;        // float4 index within input row
    unsigned hl = t >> 7;         // 0/1: row within pair
    const float4* s4 = (const float4*)sbuf;
    float4 a  = s4[(0 * 2 + hl) * 128 + wq];
    float4 bb = s4[(1 * 2 + hl) * 128 + wq];
    float4 c  = s4[(2 * 2 + hl) * 128 + wq];
    float4 d  = s4[(3 * 2 + hl) * 128 + wq];

    __syncthreads();   // all reads done before the buffer is overwritten

    // ---- compute + stage output (4 rows x 1024 floats = 16KB) ----
    float4 r0a, r0b, r1a, r1b;
    haar4(a.x, bb.x, c.x, d.x, r0a.x, r0a.y, r1a.x, r1a.y);
    haar4(a.y, bb.y, c.y, d.y, r0a.z, r0a.w, r1a.z, r1a.w);
    haar4(a.z, bb.z, c.z, d.z, r0b.x, r0b.y, r1b.x, r1b.y);
    haar4(a.w, bb.w, c.w, d.w, r0b.z, r0b.w, r1b.z, r1b.w);

    float4* orow0 = (float4*)(sbuf + (2 * hl)     * (2 * S)) + 2 * wq;
    float4* orow1 = (float4*)(sbuf + (2 * hl + 1) * (2 * S)) + 2 * wq;
    orow0[0] = r0a;
    orow0[1] = r0b;
    orow1[0] = r1a;
    orow1[1] = r1b;

    __syncthreads();

    // ---- single 16KB bulk store: output rows 4k .. 4k+3 ----
    if (t == 0) {
        asm volatile("fence.proxy.async.shared::cta;" ::: "memory");
        float* gdst = out + ((size_t)n * 2 * S + (size_t)4 * k) * (2 * S);
        asm volatile(
            "cp.async.bulk.global.shared::cta.bulk_group [%0], [%1], %2;"
            :: "l"(gdst), "r"(smem_u32(sbuf)),
               "r"((unsigned)(4 * 2 * S * sizeof(float)))
            : "memory");
        asm volatile("cp.async.bulk.commit_group;" ::: "memory");
        asm volatile("cp.async.bulk.wait_group 0;" ::: "memory");
    }
}

extern "C" void kernel_launch(void* const* d_in, const int* in_sizes, int n_in,
                              void* d_out, int out_size) {
    const float* x = (const float*)d_in[0];
    float* out = (float*)d_out;
    // one CTA per (n, input-row-pair): 32 * 256 = 8192 CTAs
    haar_recon_kernel<<<NIMG * (S / 2), 256>>>(x, out);
}